// round 7
// baseline (speedup 1.0000x reference)
#include <cuda_runtime.h>
#include <cuda_bf16.h>
#include <cstdint>
#include <cstddef>

// ===================== problem constants =====================
static constexpr int IN_F    = 4096;
static constexpr int OUT_F   = 4096;
static constexpr int RANK    = 16;
static constexpr int M_TOTAL = 4 * 2048;     // 8192 rows of x

static constexpr int THREADS = 256;

// ---- tcgen05 path tiling: CTA computes 256x256 (two 128-row M-tiles, shared W) ----
static constexpr int NT_TC = 256;
static constexpr int KC_TC = 32;             // K per stage; row = [hi 64B | lo 64B] = 128B SW128
static constexpr int NK_TC = IN_F / KC_TC;   // 128
// stage layout: A0 rows 0-127 @0 (16KB), A1 rows 128-255 @16K, W 256 rows @32K (32KB)
static constexpr int SW_OFF  = 32768;
static constexpr int STG_TC  = 65536;
static constexpr int HDR_TC  = 2048;         // [0,16) tmem ptr, [64, 64+128*8) mbarriers
static constexpr int NSTAGE  = 3;
static constexpr int SMEM_DYN = HDR_TC + NSTAGE * STG_TC;   // 198656

// idesc: kind::f16, bf16 x bf16 -> f32, M=128, N=256, K-major both
static constexpr uint32_t IDESC_TC =
    (1u << 4) | (1u << 7) | (1u << 10) | ((NT_TC / 8u) << 17) | ((128 / 16u) << 24);

// ---- fallback (mma.sync): 4 tiles of 128x128 per CTA ----
static constexpr int KC_FB = 32;
static constexpr int NK_FB = IN_F / KC_FB;   // 128
static constexpr int ROWH  = 40;             // padded row stride in bf16 (80 B)
static constexpr int AH_B  = 0;
static constexpr int AL_B  = 128 * ROWH * 2;
static constexpr int BH_B  = 2 * 128 * ROWH * 2;
static constexpr int BL_B  = 3 * 128 * ROWH * 2;
static constexpr int STG_FB = 4 * 128 * ROWH * 2;    // 40960
static constexpr int NSTAGE_FB = 3;                  // 122880 <= SMEM_DYN

// ===================== scratch (__device__ globals; no cudaMalloc) ===========
__device__ __nv_bfloat16 g_Wh[(size_t)OUT_F * IN_F];
__device__ __nv_bfloat16 g_Wl[(size_t)OUT_F * IN_F];
__device__ __nv_bfloat16 g_Xh[(size_t)M_TOTAL * IN_F];
__device__ __nv_bfloat16 g_Xl[(size_t)M_TOTAL * IN_F];

// ===================== common helpers =====================
__device__ __forceinline__ uint32_t smem_u32(const void* p) {
    uint32_t a;
    asm("{ .reg .u64 t; cvta.to.shared.u64 t, %1; cvt.u32.u64 %0, t; }" : "=r"(a) : "l"(p));
    return a;
}
__device__ __forceinline__ void cp16(uint32_t sdst, const void* gsrc) {
    asm volatile("cp.async.cg.shared.global [%0], [%1], 16;" :: "r"(sdst), "l"(gsrc));
}
#define CP_COMMIT() asm volatile("cp.async.commit_group;" ::: "memory")
#define CP_WAIT(n)  asm volatile("cp.async.wait_group %0;" :: "n"(n) : "memory")

__device__ __forceinline__ void split2bf(float v, uint16_t& h, uint16_t& l) {
    __nv_bfloat16 hb = __float2bfloat16(v);
    float r = v - __bfloat162float(hb);
    __nv_bfloat16 lb = __float2bfloat16(r);
    h = *reinterpret_cast<uint16_t*>(&hb);
    l = *reinterpret_cast<uint16_t*>(&lb);
}
__device__ __forceinline__ uint32_t pr(uint16_t lo, uint16_t hi) {
    return (uint32_t)lo | ((uint32_t)hi << 16);
}
__device__ __forceinline__ uint32_t swz(uint32_t off) { return off ^ ((off >> 3) & 0x70); }

// ===================== tcgen05 machinery (sm_103a cubin only) ================
#if defined(__CUDA_ARCH_FEAT_SM103_ALL)
__device__ __forceinline__ uint32_t elect_one() {
    uint32_t p;
    asm volatile("{\n\t.reg .pred p;\n\telect.sync _|p, 0xFFFFFFFF;\n\tselp.b32 %0, 1, 0, p;\n\t}"
                 : "=r"(p));
    return p;
}
#define MBARRIER_INIT(addr, cnt) \
    asm volatile("mbarrier.init.shared.b64 [%0], %1;" :: "r"(addr), "r"(cnt) : "memory")
#define MBARRIER_WAIT_PARITY(mbar, par) do {                                             \
    uint32_t _m = (uint32_t)(mbar); uint32_t _p = (uint32_t)(par); uint32_t _d;          \
    asm volatile("{\n\t.reg .pred p;\n\t"                                                \
        "mbarrier.try_wait.parity.acquire.cta.shared::cta.b64 p, [%1], %2;\n\t"          \
        "selp.b32 %0, 1, 0, p;\n\t}" : "=r"(_d) : "r"(_m), "r"(_p) : "memory");          \
    if (!_d) {                                                                           \
        asm volatile("{\n\t.reg .pred P1;\n\tWL_%=: \n\t"                                \
            "mbarrier.try_wait.parity.acquire.cta.shared::cta.b64 P1, [%0], %1, 0x989680;\n\t" \
            "@P1 bra.uni WD_%=;\n\tbra.uni WL_%=;\n\tWD_%=: \n\t}"                       \
            :: "r"(_m), "r"(_p) : "memory");                                             \
    }                                                                                    \
} while (0)
#define TCGEN05_ALLOC(sa, n)  asm volatile("tcgen05.alloc.cta_group::1.sync.aligned.shared::cta.b32 [%0], %1;" :: "r"((uint32_t)(sa)), "r"((uint32_t)(n)) : "memory")
#define TCGEN05_RELQ()        asm volatile("tcgen05.relinquish_alloc_permit.cta_group::1.sync.aligned;")
#define TCGEN05_DEALLOC(t, n) asm volatile("tcgen05.dealloc.cta_group::1.sync.aligned.b32 %0, %1;" :: "r"(t), "r"((uint32_t)(n)))
#define TCGEN05_COMMIT(mb)    asm volatile("tcgen05.commit.cta_group::1.mbarrier::arrive::one.shared::cluster.b64 [%0];" :: "r"((uint32_t)(mb)) : "memory")
#define TCGEN05_FENCE_AFTER()  asm volatile("tcgen05.fence::after_thread_sync;" ::: "memory")
#define TCGEN05_FENCE_BEFORE() asm volatile("tcgen05.fence::before_thread_sync;" ::: "memory")
#define TCGEN05_WAIT_LD()      asm volatile("tcgen05.wait::ld.sync.aligned;" ::: "memory")
#define FENCE_PROXY()          asm volatile("fence.proxy.async.shared::cta;" ::: "memory")

#define TCGEN05_LD_X32(r, ta) \
    asm volatile( \
        "tcgen05.ld.sync.aligned.32x32b.x32.b32 " \
        "{%0, %1, %2, %3, %4, %5, %6, %7, " \
        " %8, %9, %10, %11, %12, %13, %14, %15, " \
        " %16, %17, %18, %19, %20, %21, %22, %23, " \
        " %24, %25, %26, %27, %28, %29, %30, %31}, [%32];" \
        : "=r"((r)[0]),  "=r"((r)[1]),  "=r"((r)[2]),  "=r"((r)[3]), \
          "=r"((r)[4]),  "=r"((r)[5]),  "=r"((r)[6]),  "=r"((r)[7]), \
          "=r"((r)[8]),  "=r"((r)[9]),  "=r"((r)[10]), "=r"((r)[11]), \
          "=r"((r)[12]), "=r"((r)[13]), "=r"((r)[14]), "=r"((r)[15]), \
          "=r"((r)[16]), "=r"((r)[17]), "=r"((r)[18]), "=r"((r)[19]), \
          "=r"((r)[20]), "=r"((r)[21]), "=r"((r)[22]), "=r"((r)[23]), \
          "=r"((r)[24]), "=r"((r)[25]), "=r"((r)[26]), "=r"((r)[27]), \
          "=r"((r)[28]), "=r"((r)[29]), "=r"((r)[30]), "=r"((r)[31]) \
        : "r"(ta))

static constexpr uint64_t SMEM_DESC_BASE_SW128 =
    (uint64_t(2) << 61) | (uint64_t(1) << 46) | (uint64_t(64) << 32) | (uint64_t(1) << 16);
#define MAKE_SMEM_DESC(ba) (SMEM_DESC_BASE_SW128 | ((uint64_t)((ba) >> 4) & 0x3FFF))

__device__ __forceinline__ void mma_f16_ss(uint32_t d, uint64_t a, uint64_t b,
                                           uint32_t idesc, uint32_t acc) {
    asm volatile(
        "{\n\t.reg .pred p;\n\tsetp.ne.u32 p, %4, 0;\n\t"
        "tcgen05.mma.cta_group::1.kind::f16 [%0], %1, %2, %3, {%5, %5, %5, %5}, p;\n\t}"
        :: "r"(d), "l"(a), "l"(b), "r"(idesc), "r"(acc), "r"(0u) : "memory");
}
#else
// family-pass only: ldmatrix/mma.sync helpers
__device__ __forceinline__ void ldm4(uint32_t* r, uint32_t addr) {
    asm volatile("ldmatrix.sync.aligned.m8n8.x4.shared.b16 {%0,%1,%2,%3}, [%4];"
                 : "=r"(r[0]), "=r"(r[1]), "=r"(r[2]), "=r"(r[3]) : "r"(addr));
}
__device__ __forceinline__ void mma16816(float* d, const uint32_t* a, const uint32_t* b) {
    asm volatile(
        "mma.sync.aligned.m16n8k16.row.col.f32.bf16.bf16.f32 "
        "{%0,%1,%2,%3}, {%4,%5,%6,%7}, {%8,%9}, {%0,%1,%2,%3};"
        : "+f"(d[0]), "+f"(d[1]), "+f"(d[2]), "+f"(d[3])
        : "r"(a[0]), "r"(a[1]), "r"(a[2]), "r"(a[3]), "r"(b[0]), "r"(b[1]));
}
#endif

// ===================== prep: x -> bf16 hi/lo =====================
__global__ void __launch_bounds__(256) prep_x(const float* __restrict__ x) {
    size_t i0 = ((size_t)blockIdx.x * 256 + threadIdx.x) * 8;
    float4 a = *reinterpret_cast<const float4*>(x + i0);
    float4 b = *reinterpret_cast<const float4*>(x + i0 + 4);
    float v[8] = {a.x, a.y, a.z, a.w, b.x, b.y, b.z, b.w};
    uint16_t h[8], l[8];
    #pragma unroll
    for (int e = 0; e < 8; ++e) split2bf(v[e], h[e], l[e]);
    *reinterpret_cast<uint4*>(&g_Xh[i0]) =
        make_uint4(pr(h[0], h[1]), pr(h[2], h[3]), pr(h[4], h[5]), pr(h[6], h[7]));
    *reinterpret_cast<uint4*>(&g_Xl[i0]) =
        make_uint4(pr(l[0], l[1]), pr(l[2], l[3]), pr(l[4], l[5]), pr(l[6], l[7]));
}

// ===================== prep: W' = W + (U*s)V^T -> bf16 hi/lo ==================
__global__ void __launch_bounds__(256) prep_w(
    const float* __restrict__ W, const float* __restrict__ U,
    const float* __restrict__ s, const float* __restrict__ V)
{
    __shared__ float Us[64][16];
    const int tid    = threadIdx.x;
    const int o_base = blockIdx.y * 64;
    const int i_base = blockIdx.x * 256;

    for (int t = tid; t < 64 * 16; t += 256) {
        int ol = t >> 4, r = t & 15;
        Us[ol][r] = U[(size_t)(o_base + ol) * RANK + r] * s[r];
    }
    const int i = i_base + tid;
    float4 q0 = *reinterpret_cast<const float4*>(V + (size_t)i * RANK + 0);
    float4 q1 = *reinterpret_cast<const float4*>(V + (size_t)i * RANK + 4);
    float4 q2 = *reinterpret_cast<const float4*>(V + (size_t)i * RANK + 8);
    float4 q3 = *reinterpret_cast<const float4*>(V + (size_t)i * RANK + 12);
    float vr[16] = {q0.x, q0.y, q0.z, q0.w, q1.x, q1.y, q1.z, q1.w,
                    q2.x, q2.y, q2.z, q2.w, q3.x, q3.y, q3.z, q3.w};
    __syncthreads();

    for (int ol = 0; ol < 64; ++ol) {
        const int o = o_base + ol;
        float acc = W[(size_t)o * IN_F + i];
        #pragma unroll
        for (int r = 0; r < 16; ++r) acc += Us[ol][r] * vr[r];
        uint16_t h, l;
        split2bf(acc, h, l);
        g_Wh[(size_t)o * IN_F + i] = *reinterpret_cast<__nv_bfloat16*>(&h);
        g_Wl[(size_t)o * IN_F + i] = *reinterpret_cast<__nv_bfloat16*>(&l);
    }
}

// ===================== GEMM kernel =====================
// grid (16, 32), 256 threads. TC path: 256x256 per CTA (two M-tiles, shared W).
__global__ void __launch_bounds__(THREADS, 1) gemm_kernel(float* __restrict__ out)
{
    extern __shared__ char smem[];
    const uint32_t sb = smem_u32(smem);
    const int tid  = threadIdx.x;
    const int lane = tid & 31;
    const int wid  = tid >> 5;
    const int m_base = blockIdx.y * 256;

#if defined(__CUDA_ARCH_FEAT_SM103_ALL)
    // ===================== tcgen05 path =====================
    const int n_base = blockIdx.x * NT_TC;
    const uint32_t MB = sb + 64;              // 128 single-use mbarriers

    if (tid == 0) {
        for (int i = 0; i < NK_TC; ++i) MBARRIER_INIT(MB + i * 8, 1);
    }
    if (wid == 0) {                           // alloc THEN relinquish (no race)
        TCGEN05_ALLOC(sb + 0, 512);
        TCGEN05_RELQ();
    }
    __syncthreads();
    uint32_t tmem;
    asm volatile("ld.shared.b32 %0, [%1];" : "=r"(tmem) : "r"(sb + 0));

    // stage fill: 4096 16B chunks (A: 256 rows, W: 256 rows; row = [hi 64B | lo 64B])
    auto issue = [&](int st, int kidx) {
        const uint32_t stb = sb + HDR_TC + st * STG_TC;
        const int k0 = kidx * KC_TC;
        #pragma unroll
        for (int j = 0; j < 16; ++j) {
            int t    = tid + j * 256;
            int row  = t >> 3;                 // 0..511
            int ch   = t & 7;
            int half = ch >> 2;                // 0 = hi, 1 = lo
            int c    = ch & 3;                 // 16B chunk within 64B
            uint32_t within = swz((uint32_t)((row & 255) * 128 + half * 64 + c * 16));
            if (row < 256) {                   // A (both m-tiles, contiguous 32KB)
                const __nv_bfloat16* src = half ? g_Xl : g_Xh;
                cp16(stb + within, src + (size_t)(m_base + row) * IN_F + k0 + c * 8);
            } else {                           // W
                const __nv_bfloat16* src = half ? g_Wl : g_Wh;
                cp16(stb + SW_OFF + within, src + (size_t)(n_base + (row - 256)) * IN_F + k0 + c * 8);
            }
        }
    };

    // prologue: stages 0,1
    issue(0, 0); CP_COMMIT();
    issue(1, 1); CP_COMMIT();

    for (int it = 0; it < NK_TC; ++it) {
        const int cur = it % NSTAGE;
        // MMA(it-1) reads stage (it-1)%3 == (it+2)%3 which loads for it+2 overwrite
        if (it >= 1) MBARRIER_WAIT_PARITY(MB + (it - 1) * 8, 0);
        if (it + 2 < NK_TC) issue((it + 2) % NSTAGE, it + 2);
        CP_COMMIT();
        CP_WAIT(2);                 // stage cur resident
        FENCE_PROXY();
        __syncthreads();
        if (wid == 0) {
            TCGEN05_FENCE_AFTER();
            if (elect_one()) {
                const uint32_t stb = sb + HDR_TC + cur * STG_TC;
                const uint64_t dW  = MAKE_SMEM_DESC(stb + SW_OFF);
                const uint32_t first = (it == 0) ? 0u : 1u;
                #pragma unroll
                for (int mt = 0; mt < 2; ++mt) {
                    const uint64_t dA = MAKE_SMEM_DESC(stb + mt * 16384);
                    const uint32_t D  = tmem + mt * 256;
                    // hi|lo within row: hi at +0 (k-steps +0,+2), lo at +4 (64B)
                    mma_f16_ss(D, dA + 0, dW + 0, IDESC_TC, first);  // xh*Wh k0
                    mma_f16_ss(D, dA + 2, dW + 2, IDESC_TC, 1u);     // xh*Wh k1
                    mma_f16_ss(D, dA + 0, dW + 4, IDESC_TC, 1u);     // xh*Wl k0
                    mma_f16_ss(D, dA + 2, dW + 6, IDESC_TC, 1u);     // xh*Wl k1
                    mma_f16_ss(D, dA + 4, dW + 0, IDESC_TC, 1u);     // xl*Wh k0
                    mma_f16_ss(D, dA + 6, dW + 2, IDESC_TC, 1u);     // xl*Wh k1
                }
                TCGEN05_COMMIT(MB + it * 8);
            }
        }
        __syncthreads();
    }
    MBARRIER_WAIT_PARITY(MB + (NK_TC - 1) * 8, 0);
    TCGEN05_FENCE_AFTER();

    // epilogue: warp w: rows (w&3)*32+lane of each m-tile, col half (w>>2)*128
    {
        const int sub = wid & 3;
        const int q   = wid >> 2;
        #pragma unroll
        for (int mt = 0; mt < 2; ++mt) {
            const int row = m_base + mt * 128 + sub * 32 + lane;
            #pragma unroll
            for (int cc = 0; cc < 4; ++cc) {
                uint32_t regs[32];
                const uint32_t col0 = (uint32_t)(q * 128 + cc * 32);
                TCGEN05_LD_X32(regs, tmem + mt * 256 + col0);
                TCGEN05_WAIT_LD();
                float* dst = out + (size_t)row * OUT_F + n_base + col0;
                #pragma unroll
                for (int j = 0; j < 32; j += 4)
                    *reinterpret_cast<float4*>(dst + j) =
                        make_float4(__uint_as_float(regs[j]), __uint_as_float(regs[j + 1]),
                                    __uint_as_float(regs[j + 2]), __uint_as_float(regs[j + 3]));
            }
        }
    }
    TCGEN05_FENCE_BEFORE();
    __syncthreads();
    if (wid == 0) TCGEN05_DEALLOC(tmem, 512);

#else
    // ===================== fallback (mma.sync), 4 tiles of 128x128 =============
    const int wm = wid & 3;
    const int wn = wid >> 2;

    for (int mhalf = 0; mhalf < 2; ++mhalf)
    for (int nhalf = 0; nhalf < 2; ++nhalf) {
        const int mb = m_base + mhalf * 128;
        const int n_base_fb = (blockIdx.x * 2 + nhalf) * 128;
        __syncthreads();   // protect stage reuse across tiles

        auto issue = [&](int st, int kidx) {
            const uint32_t stb = sb + st * STG_FB;
            const int k0 = kidx * KC_FB;
            const int r0 = tid >> 2, c = tid & 3;
            #pragma unroll
            for (int j = 0; j < 2; ++j) {
                int r = r0 + j * 64;
                uint32_t rowoff = (uint32_t)(r * (ROWH * 2) + c * 16);
                size_t gx = (size_t)(mb + r) * IN_F + k0 + c * 8;
                size_t gw = (size_t)(n_base_fb + r) * IN_F + k0 + c * 8;
                cp16(stb + AH_B + rowoff, &g_Xh[gx]);
                cp16(stb + AL_B + rowoff, &g_Xl[gx]);
                cp16(stb + BH_B + rowoff, &g_Wh[gw]);
                cp16(stb + BL_B + rowoff, &g_Wl[gw]);
            }
        };

        issue(0, 0); CP_COMMIT();
        issue(1, 1); CP_COMMIT();

        float acc[2][8][4];
        #pragma unroll
        for (int a = 0; a < 2; ++a)
            #pragma unroll
            for (int b = 0; b < 8; ++b)
                #pragma unroll
                for (int cidx = 0; cidx < 4; ++cidx) acc[a][b][cidx] = 0.f;

        const int aRow  = wm * 32 + (lane & 15);
        const int aColH = (lane >> 4) * 8;
        const int bIdx  = lane & 7;
        const int bGrp  = lane >> 3;
        const int bRow  = wn * 64 + ((bGrp & 2) << 2) + bIdx;
        const int bColH = (bGrp & 1) * 8;

        for (int i = 0; i < NK_FB; ++i) {
            CP_WAIT(1);
            __syncthreads();
            if (i + 2 < NK_FB) issue((i + 2) % NSTAGE_FB, i + 2);
            CP_COMMIT();

            const uint32_t stb = sb + (i % NSTAGE_FB) * STG_FB;
            #pragma unroll
            for (int k16 = 0; k16 < 2; ++k16) {
                uint32_t ah[2][4], al[2][4];
                #pragma unroll
                for (int mt = 0; mt < 2; ++mt) {
                    uint32_t off = (uint32_t)((aRow + mt * 16) * (ROWH * 2) +
                                              (k16 * 16 + aColH) * 2);
                    ldm4(ah[mt], stb + AH_B + off);
                    ldm4(al[mt], stb + AL_B + off);
                }
                #pragma unroll
                for (int j = 0; j < 4; ++j) {
                    uint32_t off = (uint32_t)((bRow + j * 16) * (ROWH * 2) +
                                              (k16 * 16 + bColH) * 2);
                    uint32_t bh[4];
                    ldm4(bh, stb + BH_B + off);
                    #pragma unroll
                    for (int mt = 0; mt < 2; ++mt) {
                        mma16816(acc[mt][2 * j + 0], ah[mt], bh + 0);
                        mma16816(acc[mt][2 * j + 1], ah[mt], bh + 2);
                        mma16816(acc[mt][2 * j + 0], al[mt], bh + 0);
                        mma16816(acc[mt][2 * j + 1], al[mt], bh + 2);
                    }
                }
                #pragma unroll
                for (int j = 0; j < 4; ++j) {
                    uint32_t off = (uint32_t)((bRow + j * 16) * (ROWH * 2) +
                                              (k16 * 16 + bColH) * 2);
                    uint32_t bl[4];
                    ldm4(bl, stb + BL_B + off);
                    #pragma unroll
                    for (int mt = 0; mt < 2; ++mt) {
                        mma16816(acc[mt][2 * j + 0], ah[mt], bl + 0);
                        mma16816(acc[mt][2 * j + 1], ah[mt], bl + 2);
                    }
                }
            }
        }

        #pragma unroll
        for (int mt = 0; mt < 2; ++mt) {
            const int row0 = mb + wm * 32 + mt * 16 + (lane >> 2);
            #pragma unroll
            for (int nb = 0; nb < 8; ++nb) {
                const int col = n_base_fb + wn * 64 + nb * 8 + (lane & 3) * 2;
                *reinterpret_cast<float2*>(out + (size_t)row0 * OUT_F + col) =
                    make_float2(acc[mt][nb][0], acc[mt][nb][1]);
                *reinterpret_cast<float2*>(out + (size_t)(row0 + 8) * OUT_F + col) =
                    make_float2(acc[mt][nb][2], acc[mt][nb][3]);
            }
        }
    }
#endif
}

// ===================== harness entry =====================
extern "C" void kernel_launch(void* const* d_in, const int* in_sizes, int n_in,
                              void* d_out, int out_size)
{
    const float* x = (const float*)d_in[0];
    const float* W = (const float*)d_in[1];
    const float* U = (const float*)d_in[2];
    const float* s = (const float*)d_in[3];
    const float* V = (const float*)d_in[4];
    float* out = (float*)d_out;
    (void)in_sizes; (void)n_in; (void)out_size;

    prep_x<<<(M_TOTAL * IN_F) / (256 * 8), 256>>>(x);
    prep_w<<<dim3(IN_F / 256, OUT_F / 64), 256>>>(W, U, s, V);

    cudaFuncSetAttribute(gemm_kernel, cudaFuncAttributeMaxDynamicSharedMemorySize, SMEM_DYN);
    gemm_kernel<<<dim3(OUT_F / NT_TC, M_TOTAL / 256), THREADS, SMEM_DYN>>>(out);
}

// round 8
// speedup vs baseline: 1.4895x; 1.4895x over previous
#include <cuda_runtime.h>
#include <cuda_bf16.h>
#include <cstdint>
#include <cstddef>

// ===================== problem constants =====================
static constexpr int IN_F    = 4096;
static constexpr int OUT_F   = 4096;
static constexpr int RANK    = 16;
static constexpr int M_TOTAL = 4 * 2048;     // 8192 rows of x

static constexpr int THREADS = 256;

// ---- tcgen05 path tiling: CTA computes 256x256 (two 128-row M-tiles, shared W) ----
static constexpr int NT_TC = 256;
static constexpr int KC_TC = 32;             // K per stage; row = [hi 64B | lo 64B] = 128B SW128
static constexpr int NK_TC = IN_F / KC_TC;   // 128
// stage layout: A0 rows 0-127 @0 (16KB), A1 rows 128-255 @16K, W 256 rows @32K (32KB)
static constexpr int SW_OFF  = 32768;
static constexpr int STG_TC  = 65536;
static constexpr int HDR_TC  = 2048;         // [0,16) tmem ptr, [64, 64+128*8) mbarriers
static constexpr int NSTAGE  = 3;
static constexpr int SMEM_DYN = HDR_TC + NSTAGE * STG_TC;   // 198656

// idesc: kind::f16, bf16 x bf16 -> f32, M=128, N=256, K-major both
static constexpr uint32_t IDESC_TC =
    (1u << 4) | (1u << 7) | (1u << 10) | ((NT_TC / 8u) << 17) | ((128 / 16u) << 24);

// ---- fallback (mma.sync): 4 tiles of 128x128 per CTA ----
static constexpr int KC_FB = 32;
static constexpr int NK_FB = IN_F / KC_FB;   // 128
static constexpr int ROWH  = 40;             // padded row stride in bf16 (80 B)
static constexpr int AH_B  = 0;
static constexpr int AL_B  = 128 * ROWH * 2;
static constexpr int BH_B  = 2 * 128 * ROWH * 2;
static constexpr int BL_B  = 3 * 128 * ROWH * 2;
static constexpr int STG_FB = 4 * 128 * ROWH * 2;    // 40960
static constexpr int NSTAGE_FB = 3;                  // 122880 <= SMEM_DYN

// ===================== scratch (__device__ globals; no cudaMalloc) ===========
__device__ __nv_bfloat16 g_Wh[(size_t)OUT_F * IN_F];
__device__ __nv_bfloat16 g_Wl[(size_t)OUT_F * IN_F];
__device__ __nv_bfloat16 g_Xh[(size_t)M_TOTAL * IN_F];
__device__ __nv_bfloat16 g_Xl[(size_t)M_TOTAL * IN_F];

// ===================== common helpers =====================
__device__ __forceinline__ uint32_t smem_u32(const void* p) {
    uint32_t a;
    asm("{ .reg .u64 t; cvta.to.shared.u64 t, %1; cvt.u32.u64 %0, t; }" : "=r"(a) : "l"(p));
    return a;
}
__device__ __forceinline__ void cp16(uint32_t sdst, const void* gsrc) {
    asm volatile("cp.async.cg.shared.global [%0], [%1], 16;" :: "r"(sdst), "l"(gsrc));
}
#define CP_COMMIT() asm volatile("cp.async.commit_group;" ::: "memory")
#define CP_WAIT(n)  asm volatile("cp.async.wait_group %0;" :: "n"(n) : "memory")

__device__ __forceinline__ void split2bf(float v, uint16_t& h, uint16_t& l) {
    __nv_bfloat16 hb = __float2bfloat16(v);
    float r = v - __bfloat162float(hb);
    __nv_bfloat16 lb = __float2bfloat16(r);
    h = *reinterpret_cast<uint16_t*>(&hb);
    l = *reinterpret_cast<uint16_t*>(&lb);
}
__device__ __forceinline__ uint32_t pr(uint16_t lo, uint16_t hi) {
    return (uint32_t)lo | ((uint32_t)hi << 16);
}
__device__ __forceinline__ uint32_t swz(uint32_t off) { return off ^ ((off >> 3) & 0x70); }

// ===================== tcgen05 machinery (sm_103a cubin only) ================
#if defined(__CUDA_ARCH_FEAT_SM103_ALL)
__device__ __forceinline__ uint32_t elect_one() {
    uint32_t p;
    asm volatile("{\n\t.reg .pred p;\n\telect.sync _|p, 0xFFFFFFFF;\n\tselp.b32 %0, 1, 0, p;\n\t}"
                 : "=r"(p));
    return p;
}
#define MBARRIER_INIT(addr, cnt) \
    asm volatile("mbarrier.init.shared.b64 [%0], %1;" :: "r"(addr), "r"(cnt) : "memory")
#define MBARRIER_WAIT_PARITY(mbar, par) do {                                             \
    uint32_t _m = (uint32_t)(mbar); uint32_t _p = (uint32_t)(par); uint32_t _d;          \
    asm volatile("{\n\t.reg .pred p;\n\t"                                                \
        "mbarrier.try_wait.parity.acquire.cta.shared::cta.b64 p, [%1], %2;\n\t"          \
        "selp.b32 %0, 1, 0, p;\n\t}" : "=r"(_d) : "r"(_m), "r"(_p) : "memory");          \
    if (!_d) {                                                                           \
        asm volatile("{\n\t.reg .pred P1;\n\tWL_%=: \n\t"                                \
            "mbarrier.try_wait.parity.acquire.cta.shared::cta.b64 P1, [%0], %1, 0x989680;\n\t" \
            "@P1 bra.uni WD_%=;\n\tbra.uni WL_%=;\n\tWD_%=: \n\t}"                       \
            :: "r"(_m), "r"(_p) : "memory");                                             \
    }                                                                                    \
} while (0)
#define TCGEN05_ALLOC(sa, n)  asm volatile("tcgen05.alloc.cta_group::1.sync.aligned.shared::cta.b32 [%0], %1;" :: "r"((uint32_t)(sa)), "r"((uint32_t)(n)) : "memory")
#define TCGEN05_RELQ()        asm volatile("tcgen05.relinquish_alloc_permit.cta_group::1.sync.aligned;")
#define TCGEN05_DEALLOC(t, n) asm volatile("tcgen05.dealloc.cta_group::1.sync.aligned.b32 %0, %1;" :: "r"(t), "r"((uint32_t)(n)))
#define TCGEN05_COMMIT(mb)    asm volatile("tcgen05.commit.cta_group::1.mbarrier::arrive::one.shared::cluster.b64 [%0];" :: "r"((uint32_t)(mb)) : "memory")
#define TCGEN05_FENCE_AFTER()  asm volatile("tcgen05.fence::after_thread_sync;" ::: "memory")
#define TCGEN05_FENCE_BEFORE() asm volatile("tcgen05.fence::before_thread_sync;" ::: "memory")
#define TCGEN05_WAIT_LD()      asm volatile("tcgen05.wait::ld.sync.aligned;" ::: "memory")
#define FENCE_PROXY()          asm volatile("fence.proxy.async.shared::cta;" ::: "memory")

#define TCGEN05_LD_X32(r, ta) \
    asm volatile( \
        "tcgen05.ld.sync.aligned.32x32b.x32.b32 " \
        "{%0, %1, %2, %3, %4, %5, %6, %7, " \
        " %8, %9, %10, %11, %12, %13, %14, %15, " \
        " %16, %17, %18, %19, %20, %21, %22, %23, " \
        " %24, %25, %26, %27, %28, %29, %30, %31}, [%32];" \
        : "=r"((r)[0]),  "=r"((r)[1]),  "=r"((r)[2]),  "=r"((r)[3]), \
          "=r"((r)[4]),  "=r"((r)[5]),  "=r"((r)[6]),  "=r"((r)[7]), \
          "=r"((r)[8]),  "=r"((r)[9]),  "=r"((r)[10]), "=r"((r)[11]), \
          "=r"((r)[12]), "=r"((r)[13]), "=r"((r)[14]), "=r"((r)[15]), \
          "=r"((r)[16]), "=r"((r)[17]), "=r"((r)[18]), "=r"((r)[19]), \
          "=r"((r)[20]), "=r"((r)[21]), "=r"((r)[22]), "=r"((r)[23]), \
          "=r"((r)[24]), "=r"((r)[25]), "=r"((r)[26]), "=r"((r)[27]), \
          "=r"((r)[28]), "=r"((r)[29]), "=r"((r)[30]), "=r"((r)[31]) \
        : "r"(ta))

static constexpr uint64_t SMEM_DESC_BASE_SW128 =
    (uint64_t(2) << 61) | (uint64_t(1) << 46) | (uint64_t(64) << 32) | (uint64_t(1) << 16);
#define MAKE_SMEM_DESC(ba) (SMEM_DESC_BASE_SW128 | ((uint64_t)((ba) >> 4) & 0x3FFF))

__device__ __forceinline__ void mma_f16_ss(uint32_t d, uint64_t a, uint64_t b,
                                           uint32_t idesc, uint32_t acc) {
    asm volatile(
        "{\n\t.reg .pred p;\n\tsetp.ne.u32 p, %4, 0;\n\t"
        "tcgen05.mma.cta_group::1.kind::f16 [%0], %1, %2, %3, {%5, %5, %5, %5}, p;\n\t}"
        :: "r"(d), "l"(a), "l"(b), "r"(idesc), "r"(acc), "r"(0u) : "memory");
}
#else
// family-pass only: ldmatrix/mma.sync helpers
__device__ __forceinline__ void ldm4(uint32_t* r, uint32_t addr) {
    asm volatile("ldmatrix.sync.aligned.m8n8.x4.shared.b16 {%0,%1,%2,%3}, [%4];"
                 : "=r"(r[0]), "=r"(r[1]), "=r"(r[2]), "=r"(r[3]) : "r"(addr));
}
__device__ __forceinline__ void mma16816(float* d, const uint32_t* a, const uint32_t* b) {
    asm volatile(
        "mma.sync.aligned.m16n8k16.row.col.f32.bf16.bf16.f32 "
        "{%0,%1,%2,%3}, {%4,%5,%6,%7}, {%8,%9}, {%0,%1,%2,%3};"
        : "+f"(d[0]), "+f"(d[1]), "+f"(d[2]), "+f"(d[3])
        : "r"(a[0]), "r"(a[1]), "r"(a[2]), "r"(a[3]), "r"(b[0]), "r"(b[1]));
}
#endif

// ===================== prep: x -> bf16 hi/lo =====================
__global__ void __launch_bounds__(256) prep_x(const float* __restrict__ x) {
    size_t i0 = ((size_t)blockIdx.x * 256 + threadIdx.x) * 8;
    float4 a = *reinterpret_cast<const float4*>(x + i0);
    float4 b = *reinterpret_cast<const float4*>(x + i0 + 4);
    float v[8] = {a.x, a.y, a.z, a.w, b.x, b.y, b.z, b.w};
    uint16_t h[8], l[8];
    #pragma unroll
    for (int e = 0; e < 8; ++e) split2bf(v[e], h[e], l[e]);
    *reinterpret_cast<uint4*>(&g_Xh[i0]) =
        make_uint4(pr(h[0], h[1]), pr(h[2], h[3]), pr(h[4], h[5]), pr(h[6], h[7]));
    *reinterpret_cast<uint4*>(&g_Xl[i0]) =
        make_uint4(pr(l[0], l[1]), pr(l[2], l[3]), pr(l[4], l[5]), pr(l[6], l[7]));
}

// ===================== prep: W' = W + (U*s)V^T -> bf16 hi/lo ==================
__global__ void __launch_bounds__(256) prep_w(
    const float* __restrict__ W, const float* __restrict__ U,
    const float* __restrict__ s, const float* __restrict__ V)
{
    __shared__ float Us[64][16];
    const int tid    = threadIdx.x;
    const int o_base = blockIdx.y * 64;
    const int i_base = blockIdx.x * 256;

    for (int t = tid; t < 64 * 16; t += 256) {
        int ol = t >> 4, r = t & 15;
        Us[ol][r] = U[(size_t)(o_base + ol) * RANK + r] * s[r];
    }
    const int i = i_base + tid;
    float4 q0 = *reinterpret_cast<const float4*>(V + (size_t)i * RANK + 0);
    float4 q1 = *reinterpret_cast<const float4*>(V + (size_t)i * RANK + 4);
    float4 q2 = *reinterpret_cast<const float4*>(V + (size_t)i * RANK + 8);
    float4 q3 = *reinterpret_cast<const float4*>(V + (size_t)i * RANK + 12);
    float vr[16] = {q0.x, q0.y, q0.z, q0.w, q1.x, q1.y, q1.z, q1.w,
                    q2.x, q2.y, q2.z, q2.w, q3.x, q3.y, q3.z, q3.w};
    __syncthreads();

    for (int ol = 0; ol < 64; ++ol) {
        const int o = o_base + ol;
        float acc = W[(size_t)o * IN_F + i];
        #pragma unroll
        for (int r = 0; r < 16; ++r) acc += Us[ol][r] * vr[r];
        uint16_t h, l;
        split2bf(acc, h, l);
        g_Wh[(size_t)o * IN_F + i] = *reinterpret_cast<__nv_bfloat16*>(&h);
        g_Wl[(size_t)o * IN_F + i] = *reinterpret_cast<__nv_bfloat16*>(&l);
    }
}

// ===================== GEMM kernel =====================
// grid (16, 32), 256 threads. TC path: 256x256 per CTA (two M-tiles, shared W).
__global__ void __launch_bounds__(THREADS, 1) gemm_kernel(float* __restrict__ out)
{
    extern __shared__ char smem[];
    const uint32_t sb = smem_u32(smem);
    const int tid  = threadIdx.x;
    const int lane = tid & 31;
    const int wid  = tid >> 5;
    const int m_base = blockIdx.y * 256;

#if defined(__CUDA_ARCH_FEAT_SM103_ALL)
    // ===================== tcgen05 path =====================
    const int n_base = blockIdx.x * NT_TC;
    const uint32_t MB = sb + 64;              // 128 single-use mbarriers

    if (tid == 0) {
        for (int i = 0; i < NK_TC; ++i) MBARRIER_INIT(MB + i * 8, 1);
    }
    if (wid == 0) {                           // alloc THEN relinquish (no race)
        TCGEN05_ALLOC(sb + 0, 512);
        TCGEN05_RELQ();
    }
    __syncthreads();
    uint32_t tmem;
    asm volatile("ld.shared.b32 %0, [%1];" : "=r"(tmem) : "r"(sb + 0));

    // stage fill: 4096 16B chunks (A: 256 rows, W: 256 rows; row = [hi 64B | lo 64B])
    auto issue = [&](int st, int kidx) {
        const uint32_t stb = sb + HDR_TC + st * STG_TC;
        const int k0 = kidx * KC_TC;
        #pragma unroll
        for (int j = 0; j < 16; ++j) {
            int t    = tid + j * 256;
            int row  = t >> 3;                 // 0..511
            int ch   = t & 7;
            int half = ch >> 2;                // 0 = hi, 1 = lo
            int c    = ch & 3;                 // 16B chunk within 64B
            uint32_t within = swz((uint32_t)((row & 255) * 128 + half * 64 + c * 16));
            if (row < 256) {                   // A (both m-tiles, contiguous 32KB)
                const __nv_bfloat16* src = half ? g_Xl : g_Xh;
                cp16(stb + within, src + (size_t)(m_base + row) * IN_F + k0 + c * 8);
            } else {                           // W
                const __nv_bfloat16* src = half ? g_Wl : g_Wh;
                cp16(stb + SW_OFF + within, src + (size_t)(n_base + (row - 256)) * IN_F + k0 + c * 8);
            }
        }
    };

    // prologue: stages 0,1 in flight; stage 0 resident before first MMA
    issue(0, 0); CP_COMMIT();
    issue(1, 1); CP_COMMIT();
    CP_WAIT(1);                 // stage 0 resident
    FENCE_PROXY();
    __syncthreads();

    for (int it = 0; it < NK_TC; ++it) {
        const int cur = it % NSTAGE;

        // 1) issue MMA(it) FIRST — stage `it` is resident; tensor pipe stays fed
        if (wid == 0) {
            TCGEN05_FENCE_AFTER();
            if (elect_one()) {
                const uint32_t stb = sb + HDR_TC + cur * STG_TC;
                const uint64_t dW  = MAKE_SMEM_DESC(stb + SW_OFF);
                const uint32_t first = (it == 0) ? 0u : 1u;
                #pragma unroll
                for (int mt = 0; mt < 2; ++mt) {
                    const uint64_t dA = MAKE_SMEM_DESC(stb + mt * 16384);
                    const uint32_t D  = tmem + mt * 256;
                    mma_f16_ss(D, dA + 0, dW + 0, IDESC_TC, first);  // xh*Wh k0
                    mma_f16_ss(D, dA + 2, dW + 2, IDESC_TC, 1u);     // xh*Wh k1
                    mma_f16_ss(D, dA + 0, dW + 4, IDESC_TC, 1u);     // xh*Wl k0
                    mma_f16_ss(D, dA + 2, dW + 6, IDESC_TC, 1u);     // xh*Wl k1
                    mma_f16_ss(D, dA + 4, dW + 0, IDESC_TC, 1u);     // xl*Wh k0
                    mma_f16_ss(D, dA + 6, dW + 2, IDESC_TC, 1u);     // xl*Wh k1
                }
                TCGEN05_COMMIT(MB + it * 8);
            }
        }

        // 2) wait MMA(it-1) done (overlaps with MMA(it) executing), then reuse its stage
        if (it + 2 < NK_TC) {
            if (it >= 1) MBARRIER_WAIT_PARITY(MB + (it - 1) * 8, 0);
            issue((it + 2) % NSTAGE, it + 2);
            CP_COMMIT();
        }

        // 3) make stage it+1 resident for next iteration's MMA
        CP_WAIT(1);
        FENCE_PROXY();
        __syncthreads();
    }
    MBARRIER_WAIT_PARITY(MB + (NK_TC - 1) * 8, 0);
    TCGEN05_FENCE_AFTER();

    // epilogue: warp w: rows (w&3)*32+lane of each m-tile, col half (w>>2)*128
    {
        const int sub = wid & 3;
        const int q   = wid >> 2;
        #pragma unroll
        for (int mt = 0; mt < 2; ++mt) {
            const int row = m_base + mt * 128 + sub * 32 + lane;
            #pragma unroll
            for (int cc = 0; cc < 4; ++cc) {
                uint32_t regs[32];
                const uint32_t col0 = (uint32_t)(q * 128 + cc * 32);
                TCGEN05_LD_X32(regs, tmem + mt * 256 + col0);
                TCGEN05_WAIT_LD();
                float* dst = out + (size_t)row * OUT_F + n_base + col0;
                #pragma unroll
                for (int j = 0; j < 32; j += 4)
                    *reinterpret_cast<float4*>(dst + j) =
                        make_float4(__uint_as_float(regs[j]), __uint_as_float(regs[j + 1]),
                                    __uint_as_float(regs[j + 2]), __uint_as_float(regs[j + 3]));
            }
        }
    }
    TCGEN05_FENCE_BEFORE();
    __syncthreads();
    if (wid == 0) TCGEN05_DEALLOC(tmem, 512);

#else
    // ===================== fallback (mma.sync), 4 tiles of 128x128 =============
    const int wm = wid & 3;
    const int wn = wid >> 2;

    for (int mhalf = 0; mhalf < 2; ++mhalf)
    for (int nhalf = 0; nhalf < 2; ++nhalf) {
        const int mb = m_base + mhalf * 128;
        const int n_base_fb = (blockIdx.x * 2 + nhalf) * 128;
        __syncthreads();   // protect stage reuse across tiles

        auto issue = [&](int st, int kidx) {
            const uint32_t stb = sb + st * STG_FB;
            const int k0 = kidx * KC_FB;
            const int r0 = tid >> 2, c = tid & 3;
            #pragma unroll
            for (int j = 0; j < 2; ++j) {
                int r = r0 + j * 64;
                uint32_t rowoff = (uint32_t)(r * (ROWH * 2) + c * 16);
                size_t gx = (size_t)(mb + r) * IN_F + k0 + c * 8;
                size_t gw = (size_t)(n_base_fb + r) * IN_F + k0 + c * 8;
                cp16(stb + AH_B + rowoff, &g_Xh[gx]);
                cp16(stb + AL_B + rowoff, &g_Xl[gx]);
                cp16(stb + BH_B + rowoff, &g_Wh[gw]);
                cp16(stb + BL_B + rowoff, &g_Wl[gw]);
            }
        };

        issue(0, 0); CP_COMMIT();
        issue(1, 1); CP_COMMIT();

        float acc[2][8][4];
        #pragma unroll
        for (int a = 0; a < 2; ++a)
            #pragma unroll
            for (int b = 0; b < 8; ++b)
                #pragma unroll
                for (int cidx = 0; cidx < 4; ++cidx) acc[a][b][cidx] = 0.f;

        const int aRow  = wm * 32 + (lane & 15);
        const int aColH = (lane >> 4) * 8;
        const int bIdx  = lane & 7;
        const int bGrp  = lane >> 3;
        const int bRow  = wn * 64 + ((bGrp & 2) << 2) + bIdx;
        const int bColH = (bGrp & 1) * 8;

        for (int i = 0; i < NK_FB; ++i) {
            CP_WAIT(1);
            __syncthreads();
            if (i + 2 < NK_FB) issue((i + 2) % NSTAGE_FB, i + 2);
            CP_COMMIT();

            const uint32_t stb = sb + (i % NSTAGE_FB) * STG_FB;
            #pragma unroll
            for (int k16 = 0; k16 < 2; ++k16) {
                uint32_t ah[2][4], al[2][4];
                #pragma unroll
                for (int mt = 0; mt < 2; ++mt) {
                    uint32_t off = (uint32_t)((aRow + mt * 16) * (ROWH * 2) +
                                              (k16 * 16 + aColH) * 2);
                    ldm4(ah[mt], stb + AH_B + off);
                    ldm4(al[mt], stb + AL_B + off);
                }
                #pragma unroll
                for (int j = 0; j < 4; ++j) {
                    uint32_t off = (uint32_t)((bRow + j * 16) * (ROWH * 2) +
                                              (k16 * 16 + bColH) * 2);
                    uint32_t bh[4];
                    ldm4(bh, stb + BH_B + off);
                    #pragma unroll
                    for (int mt = 0; mt < 2; ++mt) {
                        mma16816(acc[mt][2 * j + 0], ah[mt], bh + 0);
                        mma16816(acc[mt][2 * j + 1], ah[mt], bh + 2);
                        mma16816(acc[mt][2 * j + 0], al[mt], bh + 0);
                        mma16816(acc[mt][2 * j + 1], al[mt], bh + 2);
                    }
                }
                #pragma unroll
                for (int j = 0; j < 4; ++j) {
                    uint32_t off = (uint32_t)((bRow + j * 16) * (ROWH * 2) +
                                              (k16 * 16 + bColH) * 2);
                    uint32_t bl[4];
                    ldm4(bl, stb + BL_B + off);
                    #pragma unroll
                    for (int mt = 0; mt < 2; ++mt) {
                        mma16816(acc[mt][2 * j + 0], ah[mt], bl + 0);
                        mma16816(acc[mt][2 * j + 1], ah[mt], bl + 2);
                    }
                }
            }
        }

        #pragma unroll
        for (int mt = 0; mt < 2; ++mt) {
            const int row0 = mb + wm * 32 + mt * 16 + (lane >> 2);
            #pragma unroll
            for (int nb = 0; nb < 8; ++nb) {
                const int col = n_base_fb + wn * 64 + nb * 8 + (lane & 3) * 2;
                *reinterpret_cast<float2*>(out + (size_t)row0 * OUT_F + col) =
                    make_float2(acc[mt][nb][0], acc[mt][nb][1]);
                *reinterpret_cast<float2*>(out + (size_t)(row0 + 8) * OUT_F + col) =
                    make_float2(acc[mt][nb][2], acc[mt][nb][3]);
            }
        }
    }
#endif
}

// ===================== harness entry =====================
extern "C" void kernel_launch(void* const* d_in, const int* in_sizes, int n_in,
                              void* d_out, int out_size)
{
    const float* x = (const float*)d_in[0];
    const float* W = (const float*)d_in[1];
    const float* U = (const float*)d_in[2];
    const float* s = (const float*)d_in[3];
    const float* V = (const float*)d_in[4];
    float* out = (float*)d_out;
    (void)in_sizes; (void)n_in; (void)out_size;

    prep_x<<<(M_TOTAL * IN_F) / (256 * 8), 256>>>(x);
    prep_w<<<dim3(IN_F / 256, OUT_F / 64), 256>>>(W, U, s, V);

    cudaFuncSetAttribute(gemm_kernel, cudaFuncAttributeMaxDynamicSharedMemorySize, SMEM_DYN);
    gemm_kernel<<<dim3(OUT_F / NT_TC, M_TOTAL / 256), THREADS, SMEM_DYN>>>(out);
}